// round 4
// baseline (speedup 1.0000x reference)
#include <cuda_runtime.h>
#include <math.h>

#define D_MODEL 1024
#define SEQ     4096
#define BATCH   4
#define NROWS   (BATCH*SEQ)

// Scratch (static __device__ arrays: allocation-free per harness rules)
__device__ float g_q[NROWS*D_MODEL];
__device__ float g_k[NROWS*D_MODEL];
__device__ float g_v[NROWS*D_MODEL];
__device__ float g_cos[SEQ*(D_MODEL/2)];
__device__ float g_sin[SEQ*(D_MODEL/2)];

// ---------------------------------------------------------------------------
// RoPE table: double precision cos/sin (truth); reference's own fp32 rounding
// bounds the deviation at ~2.5e-4 absolute.
// theta = 10000^(-2*(i-1)/d)  (faithful to the reference's i-1)
// ---------------------------------------------------------------------------
__global__ void rope_table_kernel() {
    int i   = threadIdx.x;   // 0..511 pair index
    int pos = blockIdx.x;    // 0..4095
    double theta = pow(10000.0, -2.0 * ((double)i - 1.0) / (double)D_MODEL);
    double ang   = (double)pos * theta;
    g_cos[pos*(D_MODEL/2)+i] = (float)cos(ang);
    g_sin[pos*(D_MODEL/2)+i] = (float)sin(ang);
}

// ---------------------------------------------------------------------------
// QKV GEMM: C[r,c] = sum_k X[r,k] * W[c,k]   (y = x W^T)
// 128x128 tile, BK=8, 8x8 per thread, 256 threads. grid.z selects Q/K/V.
// RoPE applied in epilogue for z<2.
// ---------------------------------------------------------------------------
__global__ void __launch_bounds__(256) qkv_gemm_kernel(
    const float* __restrict__ X, const float* __restrict__ Wq,
    const float* __restrict__ Wk, const float* __restrict__ Wv)
{
    __shared__ float As[8][132];
    __shared__ float Bs[8][132];

    const int z = blockIdx.z;
    const float* __restrict__ W = (z == 0) ? Wq : (z == 1) ? Wk : Wv;
    float* __restrict__ Out     = (z == 0) ? g_q : (z == 1) ? g_k : g_v;

    const int row0 = blockIdx.y * 128;
    const int col0 = blockIdx.x * 128;
    const int tid  = threadIdx.x;
    const int tx   = tid & 15;
    const int ty   = tid >> 4;

    const int lr = tid >> 1;         // 0..127
    const int lc = (tid & 1) * 4;    // 0 or 4
    const float* Xp = X + (size_t)(row0 + lr) * D_MODEL + lc;
    const float* Wp = W + (size_t)(col0 + lr) * D_MODEL + lc;

    float acc[8][8];
    #pragma unroll
    for (int i = 0; i < 8; i++)
        #pragma unroll
        for (int j = 0; j < 8; j++) acc[i][j] = 0.f;

    for (int k0 = 0; k0 < D_MODEL; k0 += 8) {
        float4 a = *(const float4*)(Xp + k0);
        float4 b = *(const float4*)(Wp + k0);
        __syncthreads();
        As[lc+0][lr] = a.x; As[lc+1][lr] = a.y; As[lc+2][lr] = a.z; As[lc+3][lr] = a.w;
        Bs[lc+0][lr] = b.x; Bs[lc+1][lr] = b.y; Bs[lc+2][lr] = b.z; Bs[lc+3][lr] = b.w;
        __syncthreads();
        #pragma unroll
        for (int k = 0; k < 8; k++) {
            float ar[8], br[8];
            *(float4*)(ar)   = *(const float4*)(&As[k][ty*8]);
            *(float4*)(ar+4) = *(const float4*)(&As[k][ty*8+4]);
            *(float4*)(br)   = *(const float4*)(&Bs[k][tx*8]);
            *(float4*)(br+4) = *(const float4*)(&Bs[k][tx*8+4]);
            #pragma unroll
            for (int i = 0; i < 8; i++)
                #pragma unroll
                for (int j = 0; j < 8; j++)
                    acc[i][j] = fmaf(ar[i], br[j], acc[i][j]);
        }
    }

    // Epilogue: RoPE for q/k, then store
    #pragma unroll
    for (int i = 0; i < 8; i++) {
        const int r     = row0 + ty*8 + i;
        const int pos   = r & (SEQ-1);
        const int cbase = col0 + tx*8;
        if (z < 2) {
            #pragma unroll
            for (int jp = 0; jp < 4; jp++) {
                float cs = g_cos[pos*(D_MODEL/2) + (cbase>>1) + jp];
                float sn = g_sin[pos*(D_MODEL/2) + (cbase>>1) + jp];
                float e = acc[i][jp*2], o = acc[i][jp*2+1];
                acc[i][jp*2]   =  e*cs + o*sn;
                acc[i][jp*2+1] = -e*sn + o*cs;
            }
        }
        float4 s0 = make_float4(acc[i][0], acc[i][1], acc[i][2], acc[i][3]);
        float4 s1 = make_float4(acc[i][4], acc[i][5], acc[i][6], acc[i][7]);
        *(float4*)(Out + (size_t)r*D_MODEL + cbase)     = s0;
        *(float4*)(Out + (size_t)r*D_MODEL + cbase + 4) = s1;
    }
}

// ---------------------------------------------------------------------------
// Flash attention (causal), fp32 online softmax.
// Block: 16 queries x one batch. 256 threads: thread = (row r = tid>>4, cc = tid&15).
// K tile = 64 keys, D chunked by 128. Q tile fully in smem; O[16x1024] in regs
// (64 floats/thread). Bank-conflict-free smem strides.
// ---------------------------------------------------------------------------
#define QS_STRIDE 1032
#define KS_STRIDE 129
#define VS_STRIDE 132
#define PS_STRIDE 65
#define ATT_SMEM_BYTES ((16*QS_STRIDE + 64*VS_STRIDE + 16*PS_STRIDE) * 4)

__global__ void __launch_bounds__(256, 2) attention_kernel(float* __restrict__ out)
{
    extern __shared__ float sm[];
    float* Qs = sm;                       // 16 rows, stride 1032
    float* KV = sm + 16*QS_STRIDE;        // shared K (stride 129) / V (stride 132) chunk
    float* Ps = KV + 64*VS_STRIDE;        // 16 rows, stride 65

    const int b   = blockIdx.y;
    const int qt  = (gridDim.x - 1) - blockIdx.x;   // long blocks first
    const int q0  = qt * 16;
    const int tid = threadIdx.x;
    const int r   = tid >> 4;
    const int cc  = tid & 15;

    const float* Qg = g_q + (size_t)(b*SEQ + q0) * D_MODEL;
    const float* Kg = g_k + (size_t)(b*SEQ) * D_MODEL;
    const float* Vg = g_v + (size_t)(b*SEQ) * D_MODEL;

    // Load Q tile (16x1024) once
    #pragma unroll
    for (int it = 0; it < 16; it++) {
        int idx = (tid + it*256) * 4;
        int row = idx >> 10, col = idx & 1023;
        *(float4*)(Qs + row*QS_STRIDE + col) =
            *(const float4*)(Qg + (size_t)row*D_MODEL + col);
    }

    float O[64];
    #pragma unroll
    for (int i = 0; i < 64; i++) O[i] = 0.f;
    float mrow = -INFINITY, lrow = 0.f;

    const int qg     = q0 + r;
    const int ktlast = (q0 + 15) >> 6;

    for (int kt = 0; kt <= ktlast; kt++) {
        const int kb = kt * 64;

        // ---------- scores: S[16][64] over D=1024 in 8 chunks of 128 ----------
        float s0 = 0.f, s1 = 0.f, s2 = 0.f, s3 = 0.f;
        for (int dc = 0; dc < 8; dc++) {
            __syncthreads();  // previous-phase smem reads done
            #pragma unroll
            for (int it = 0; it < 8; it++) {
                int idx = (tid + it*256) * 4;
                int row = idx >> 7, col = idx & 127;
                float4 v = *(const float4*)(Kg + (size_t)(kb+row)*D_MODEL + dc*128 + col);
                float* p = KV + row*KS_STRIDE + col;
                p[0]=v.x; p[1]=v.y; p[2]=v.z; p[3]=v.w;
            }
            __syncthreads();
            const float* qrow = Qs + r*QS_STRIDE + dc*128;
            const float* kp   = KV + cc*KS_STRIDE;
            #pragma unroll
            for (int d = 0; d < 128; d += 4) {
                float q4[4];
                *(float4*)q4 = *(const float4*)(qrow + d);
                #pragma unroll
                for (int u = 0; u < 4; u++) {
                    float qv = q4[u];
                    s0 = fmaf(qv, kp[d+u],                   s0);
                    s1 = fmaf(qv, kp[16*KS_STRIDE + d+u],    s1);
                    s2 = fmaf(qv, kp[32*KS_STRIDE + d+u],    s2);
                    s3 = fmaf(qv, kp[48*KS_STRIDE + d+u],    s3);
                }
            }
        }
        const float scale = 0.03125f;  // 1/sqrt(1024)
        s0 *= scale; s1 *= scale; s2 *= scale; s3 *= scale;

        if (kb + 63 > q0) {  // causal mask needed
            if (kb + cc      > qg) s0 = -INFINITY;
            if (kb + cc + 16 > qg) s1 = -INFINITY;
            if (kb + cc + 32 > qg) s2 = -INFINITY;
            if (kb + cc + 48 > qg) s3 = -INFINITY;
        }

        // row max over 16 lanes (same-r threads are a contiguous 16-lane group)
        float tm = fmaxf(fmaxf(s0, s1), fmaxf(s2, s3));
        #pragma unroll
        for (int off = 8; off >= 1; off >>= 1)
            tm = fmaxf(tm, __shfl_xor_sync(0xffffffffu, tm, off));
        float mnew  = fmaxf(mrow, tm);
        float alpha = expf(mrow - mnew);     // first tile: exp(-inf)=0
        float p0 = expf(s0 - mnew);
        float p1 = expf(s1 - mnew);
        float p2 = expf(s2 - mnew);
        float p3 = expf(s3 - mnew);
        float ls = p0 + p1 + p2 + p3;
        #pragma unroll
        for (int off = 8; off >= 1; off >>= 1)
            ls += __shfl_xor_sync(0xffffffffu, ls, off);
        lrow = lrow * alpha + ls;
        mrow = mnew;

        Ps[r*PS_STRIDE + cc     ] = p0;
        Ps[r*PS_STRIDE + cc + 16] = p1;
        Ps[r*PS_STRIDE + cc + 32] = p2;
        Ps[r*PS_STRIDE + cc + 48] = p3;

        #pragma unroll
        for (int i = 0; i < 64; i++) O[i] *= alpha;

        // ---------- PV: O[16][1024] += P[16][64] @ V[64][1024] ----------
        for (int dc = 0; dc < 8; dc++) {
            __syncthreads();  // score reads of KV done; Ps written
            #pragma unroll
            for (int it = 0; it < 8; it++) {
                int idx = (tid + it*256) * 4;
                int row = idx >> 7, col = idx & 127;
                *(float4*)(KV + row*VS_STRIDE + col) =
                    *(const float4*)(Vg + (size_t)(kb+row)*D_MODEL + dc*128 + col);
            }
            __syncthreads();
            const int ob = 8*dc;
            #pragma unroll 4
            for (int kk = 0; kk < 64; kk++) {
                float p = Ps[r*PS_STRIDE + kk];
                const float* vrow = KV + kk*VS_STRIDE;
                float va[4], vb[4];
                *(float4*)va = *(const float4*)(vrow + cc*4);
                *(float4*)vb = *(const float4*)(vrow + 64 + cc*4);
                #pragma unroll
                for (int u = 0; u < 4; u++) {
                    O[ob+u]   = fmaf(p, va[u], O[ob+u]);
                    O[ob+4+u] = fmaf(p, vb[u], O[ob+4+u]);
                }
            }
        }
    }

    // Output: out[b, qg, :] = O / lrow
    float inv = 1.f / lrow;
    float* Og = out + (size_t)(b*SEQ + qg) * D_MODEL;
    #pragma unroll
    for (int dc = 0; dc < 8; dc++) {
        float4 a, c;
        a.x = O[8*dc+0]*inv; a.y = O[8*dc+1]*inv; a.z = O[8*dc+2]*inv; a.w = O[8*dc+3]*inv;
        c.x = O[8*dc+4]*inv; c.y = O[8*dc+5]*inv; c.z = O[8*dc+6]*inv; c.w = O[8*dc+7]*inv;
        *(float4*)(Og + dc*128 + cc*4)      = a;
        *(float4*)(Og + dc*128 + 64 + cc*4) = c;
    }
}

// ---------------------------------------------------------------------------
extern "C" void kernel_launch(void* const* d_in, const int* in_sizes, int n_in,
                              void* d_out, int out_size) {
    const float* x  = (const float*)d_in[0];
    const float* wq = (const float*)d_in[1];
    const float* wk = (const float*)d_in[2];
    const float* wv = (const float*)d_in[3];
    float* out = (float*)d_out;
    (void)in_sizes; (void)n_in; (void)out_size;

    cudaFuncSetAttribute(attention_kernel,
                         cudaFuncAttributeMaxDynamicSharedMemorySize, ATT_SMEM_BYTES);

    rope_table_kernel<<<SEQ, D_MODEL/2>>>();

    dim3 g1(D_MODEL/128, NROWS/128, 3);
    qkv_gemm_kernel<<<g1, 256>>>(x, wq, wk, wv);

    dim3 g2(SEQ/16, BATCH);
    attention_kernel<<<g2, 256, ATT_SMEM_BYTES>>>(out);
}

// round 5
// speedup vs baseline: 1.0064x; 1.0064x over previous
#include <cuda_runtime.h>
#include <math.h>

#define D_MODEL 1024
#define SEQ     4096
#define BATCH   4
#define NROWS   (BATCH*SEQ)

// Scratch (static __device__ arrays: allocation-free per harness rules)
__device__ float g_q[NROWS*D_MODEL];
__device__ float g_k[NROWS*D_MODEL];
__device__ float g_v[NROWS*D_MODEL];
__device__ float g_cos[SEQ*(D_MODEL/2)];
__device__ float g_sin[SEQ*(D_MODEL/2)];

// ---------------------------------------------------------------------------
// RoPE table: double precision cos/sin (truth); reference's own fp32 rounding
// bounds the deviation at ~2.5e-4 absolute.
// theta = 10000^(-2*(i-1)/d)  (faithful to the reference's i-1)
// ---------------------------------------------------------------------------
__global__ void rope_table_kernel() {
    int i   = threadIdx.x;   // 0..511 pair index
    int pos = blockIdx.x;    // 0..4095
    double theta = pow(10000.0, -2.0 * ((double)i - 1.0) / (double)D_MODEL);
    double ang   = (double)pos * theta;
    g_cos[pos*(D_MODEL/2)+i] = (float)cos(ang);
    g_sin[pos*(D_MODEL/2)+i] = (float)sin(ang);
}

// ---------------------------------------------------------------------------
// QKV GEMM: C[r,c] = sum_k X[r,k] * W[c,k]   (y = x W^T)
// 128x128 tile, BK=8, 8x8 per thread, 256 threads. grid.z selects Q/K/V.
// RoPE applied in epilogue for z<2.
// ---------------------------------------------------------------------------
__global__ void __launch_bounds__(256) qkv_gemm_kernel(
    const float* __restrict__ X, const float* __restrict__ Wq,
    const float* __restrict__ Wk, const float* __restrict__ Wv)
{
    __shared__ float As[8][132];
    __shared__ float Bs[8][132];

    const int z = blockIdx.z;
    const float* __restrict__ W = (z == 0) ? Wq : (z == 1) ? Wk : Wv;
    float* __restrict__ Out     = (z == 0) ? g_q : (z == 1) ? g_k : g_v;

    const int row0 = blockIdx.y * 128;
    const int col0 = blockIdx.x * 128;
    const int tid  = threadIdx.x;
    const int tx   = tid & 15;
    const int ty   = tid >> 4;

    const int lr = tid >> 1;         // 0..127
    const int lc = (tid & 1) * 4;    // 0 or 4
    const float* Xp = X + (size_t)(row0 + lr) * D_MODEL + lc;
    const float* Wp = W + (size_t)(col0 + lr) * D_MODEL + lc;

    float acc[8][8];
    #pragma unroll
    for (int i = 0; i < 8; i++)
        #pragma unroll
        for (int j = 0; j < 8; j++) acc[i][j] = 0.f;

    for (int k0 = 0; k0 < D_MODEL; k0 += 8) {
        float4 a = *(const float4*)(Xp + k0);
        float4 b = *(const float4*)(Wp + k0);
        __syncthreads();
        As[lc+0][lr] = a.x; As[lc+1][lr] = a.y; As[lc+2][lr] = a.z; As[lc+3][lr] = a.w;
        Bs[lc+0][lr] = b.x; Bs[lc+1][lr] = b.y; Bs[lc+2][lr] = b.z; Bs[lc+3][lr] = b.w;
        __syncthreads();
        #pragma unroll
        for (int k = 0; k < 8; k++) {
            float ar[8], br[8];
            *(float4*)(ar)   = *(const float4*)(&As[k][ty*8]);
            *(float4*)(ar+4) = *(const float4*)(&As[k][ty*8+4]);
            *(float4*)(br)   = *(const float4*)(&Bs[k][tx*8]);
            *(float4*)(br+4) = *(const float4*)(&Bs[k][tx*8+4]);
            #pragma unroll
            for (int i = 0; i < 8; i++)
                #pragma unroll
                for (int j = 0; j < 8; j++)
                    acc[i][j] = fmaf(ar[i], br[j], acc[i][j]);
        }
    }

    // Epilogue: RoPE for q/k, then store
    #pragma unroll
    for (int i = 0; i < 8; i++) {
        const int r     = row0 + ty*8 + i;
        const int pos   = r & (SEQ-1);
        const int cbase = col0 + tx*8;
        if (z < 2) {
            #pragma unroll
            for (int jp = 0; jp < 4; jp++) {
                float cs = g_cos[pos*(D_MODEL/2) + (cbase>>1) + jp];
                float sn = g_sin[pos*(D_MODEL/2) + (cbase>>1) + jp];
                float e = acc[i][jp*2], o = acc[i][jp*2+1];
                acc[i][jp*2]   =  e*cs + o*sn;
                acc[i][jp*2+1] = -e*sn + o*cs;
            }
        }
        float4 s0 = make_float4(acc[i][0], acc[i][1], acc[i][2], acc[i][3]);
        float4 s1 = make_float4(acc[i][4], acc[i][5], acc[i][6], acc[i][7]);
        *(float4*)(Out + (size_t)r*D_MODEL + cbase)     = s0;
        *(float4*)(Out + (size_t)r*D_MODEL + cbase + 4) = s1;
    }
}

// ---------------------------------------------------------------------------
// Flash attention (causal), fp32 online softmax.
// Block: 16 queries x one batch. 256 threads: thread = (row r = tid>>4, cc = tid&15).
// K tile = 64 keys, D chunked by 128. Q tile fully in smem; O[16x1024] in regs
// (64 floats/thread). Bank-conflict-free smem strides.
// ---------------------------------------------------------------------------
#define QS_STRIDE 1032
#define KS_STRIDE 129
#define VS_STRIDE 132
#define PS_STRIDE 65
#define ATT_SMEM_BYTES ((16*QS_STRIDE + 64*VS_STRIDE + 16*PS_STRIDE) * 4)

__global__ void __launch_bounds__(256, 2) attention_kernel(float* __restrict__ out)
{
    extern __shared__ float sm[];
    float* Qs = sm;                       // 16 rows, stride 1032
    float* KV = sm + 16*QS_STRIDE;        // shared K (stride 129) / V (stride 132) chunk
    float* Ps = KV + 64*VS_STRIDE;        // 16 rows, stride 65

    const int b   = blockIdx.y;
    const int qt  = (gridDim.x - 1) - blockIdx.x;   // long blocks first
    const int q0  = qt * 16;
    const int tid = threadIdx.x;
    const int r   = tid >> 4;
    const int cc  = tid & 15;

    const float* Qg = g_q + (size_t)(b*SEQ + q0) * D_MODEL;
    const float* Kg = g_k + (size_t)(b*SEQ) * D_MODEL;
    const float* Vg = g_v + (size_t)(b*SEQ) * D_MODEL;

    // Load Q tile (16x1024) once
    #pragma unroll
    for (int it = 0; it < 16; it++) {
        int idx = (tid + it*256) * 4;
        int row = idx >> 10, col = idx & 1023;
        *(float4*)(Qs + row*QS_STRIDE + col) =
            *(const float4*)(Qg + (size_t)row*D_MODEL + col);
    }

    float O[64];
    #pragma unroll
    for (int i = 0; i < 64; i++) O[i] = 0.f;
    float mrow = -INFINITY, lrow = 0.f;

    const int qg     = q0 + r;
    const int ktlast = (q0 + 15) >> 6;

    for (int kt = 0; kt <= ktlast; kt++) {
        const int kb = kt * 64;

        // ---------- scores: S[16][64] over D=1024 in 8 chunks of 128 ----------
        float s0 = 0.f, s1 = 0.f, s2 = 0.f, s3 = 0.f;
        for (int dc = 0; dc < 8; dc++) {
            __syncthreads();  // previous-phase smem reads done
            #pragma unroll
            for (int it = 0; it < 8; it++) {
                int idx = (tid + it*256) * 4;
                int row = idx >> 7, col = idx & 127;
                float4 v = *(const float4*)(Kg + (size_t)(kb+row)*D_MODEL + dc*128 + col);
                float* p = KV + row*KS_STRIDE + col;
                p[0]=v.x; p[1]=v.y; p[2]=v.z; p[3]=v.w;
            }
            __syncthreads();
            const float* qrow = Qs + r*QS_STRIDE + dc*128;
            const float* kp   = KV + cc*KS_STRIDE;
            #pragma unroll
            for (int d = 0; d < 128; d += 4) {
                float q4[4];
                *(float4*)q4 = *(const float4*)(qrow + d);
                #pragma unroll
                for (int u = 0; u < 4; u++) {
                    float qv = q4[u];
                    s0 = fmaf(qv, kp[d+u],                   s0);
                    s1 = fmaf(qv, kp[16*KS_STRIDE + d+u],    s1);
                    s2 = fmaf(qv, kp[32*KS_STRIDE + d+u],    s2);
                    s3 = fmaf(qv, kp[48*KS_STRIDE + d+u],    s3);
                }
            }
        }
        const float scale = 0.03125f;  // 1/sqrt(1024)
        s0 *= scale; s1 *= scale; s2 *= scale; s3 *= scale;

        if (kb + 63 > q0) {  // causal mask needed
            if (kb + cc      > qg) s0 = -INFINITY;
            if (kb + cc + 16 > qg) s1 = -INFINITY;
            if (kb + cc + 32 > qg) s2 = -INFINITY;
            if (kb + cc + 48 > qg) s3 = -INFINITY;
        }

        // row max over 16 lanes (same-r threads are a contiguous 16-lane group)
        float tm = fmaxf(fmaxf(s0, s1), fmaxf(s2, s3));
        #pragma unroll
        for (int off = 8; off >= 1; off >>= 1)
            tm = fmaxf(tm, __shfl_xor_sync(0xffffffffu, tm, off));
        float mnew  = fmaxf(mrow, tm);
        float alpha = expf(mrow - mnew);     // first tile: exp(-inf)=0
        float p0 = expf(s0 - mnew);
        float p1 = expf(s1 - mnew);
        float p2 = expf(s2 - mnew);
        float p3 = expf(s3 - mnew);
        float ls = p0 + p1 + p2 + p3;
        #pragma unroll
        for (int off = 8; off >= 1; off >>= 1)
            ls += __shfl_xor_sync(0xffffffffu, ls, off);
        lrow = lrow * alpha + ls;
        mrow = mnew;

        Ps[r*PS_STRIDE + cc     ] = p0;
        Ps[r*PS_STRIDE + cc + 16] = p1;
        Ps[r*PS_STRIDE + cc + 32] = p2;
        Ps[r*PS_STRIDE + cc + 48] = p3;

        #pragma unroll
        for (int i = 0; i < 64; i++) O[i] *= alpha;

        // ---------- PV: O[16][1024] += P[16][64] @ V[64][1024] ----------
        for (int dc = 0; dc < 8; dc++) {
            __syncthreads();  // score reads of KV done; Ps written
            #pragma unroll
            for (int it = 0; it < 8; it++) {
                int idx = (tid + it*256) * 4;
                int row = idx >> 7, col = idx & 127;
                *(float4*)(KV + row*VS_STRIDE + col) =
                    *(const float4*)(Vg + (size_t)(kb+row)*D_MODEL + dc*128 + col);
            }
            __syncthreads();
            const int ob = 8*dc;
            #pragma unroll 4
            for (int kk = 0; kk < 64; kk++) {
                float p = Ps[r*PS_STRIDE + kk];
                const float* vrow = KV + kk*VS_STRIDE;
                float va[4], vb[4];
                *(float4*)va = *(const float4*)(vrow + cc*4);
                *(float4*)vb = *(const float4*)(vrow + 64 + cc*4);
                #pragma unroll
                for (int u = 0; u < 4; u++) {
                    O[ob+u]   = fmaf(p, va[u], O[ob+u]);
                    O[ob+4+u] = fmaf(p, vb[u], O[ob+4+u]);
                }
            }
        }
    }

    // Output: out[b, qg, :] = O / lrow
    float inv = 1.f / lrow;
    float* Og = out + (size_t)(b*SEQ + qg) * D_MODEL;
    #pragma unroll
    for (int dc = 0; dc < 8; dc++) {
        float4 a, c;
        a.x = O[8*dc+0]*inv; a.y = O[8*dc+1]*inv; a.z = O[8*dc+2]*inv; a.w = O[8*dc+3]*inv;
        c.x = O[8*dc+4]*inv; c.y = O[8*dc+5]*inv; c.z = O[8*dc+6]*inv; c.w = O[8*dc+7]*inv;
        *(float4*)(Og + dc*128 + cc*4)      = a;
        *(float4*)(Og + dc*128 + 64 + cc*4) = c;
    }
}

// ---------------------------------------------------------------------------
extern "C" void kernel_launch(void* const* d_in, const int* in_sizes, int n_in,
                              void* d_out, int out_size) {
    const float* x  = (const float*)d_in[0];
    const float* wq = (const float*)d_in[1];
    const float* wk = (const float*)d_in[2];
    const float* wv = (const float*)d_in[3];
    float* out = (float*)d_out;
    (void)in_sizes; (void)n_in; (void)out_size;

    cudaFuncSetAttribute(attention_kernel,
                         cudaFuncAttributeMaxDynamicSharedMemorySize, ATT_SMEM_BYTES);

    rope_table_kernel<<<SEQ, D_MODEL/2>>>();

    dim3 g1(D_MODEL/128, NROWS/128, 3);
    qkv_gemm_kernel<<<g1, 256>>>(x, wq, wk, wv);

    dim3 g2(SEQ/16, BATCH);
    attention_kernel<<<g2, 256, ATT_SMEM_BYTES>>>(out);
}